// round 4
// baseline (speedup 1.0000x reference)
#include <cuda_runtime.h>
#include <cuda_bf16.h>
#include <cstdint>

#define BB 8
#define NN 10000
#define EE 160000
#define FF 64
#define BN (BB * NN)          // 80000 nodes
#define BE (BB * EE)          // 1280000 edges

// ---- scratch (device globals; no allocation allowed) ----
__device__ int   g_is64;
__device__ int   g_degi[BN];
__device__ float g_dinv[BN];
__device__ int   g_rowstart[BN];
__device__ int   g_cursor[BN];
__device__ int   g_row[BE];
__device__ int   g_col[BE];
__device__ int2  g_csr[BE];       // {col, norm-bits} grouped by row
__device__ float g_t[BN * FF];    // post-linear features
__device__ float g_pA[BN * FF];   // ping
__device__ float g_pB[BN * FF];   // pong

// ---------------------------------------------------------------------------
__global__ void zeroi_k(int* __restrict__ p, int n) {
    int i = blockIdx.x * blockDim.x + threadIdx.x;
    for (; i < n; i += gridDim.x * blockDim.x) p[i] = 0;
}

// Detect edge_index element width. If truly int64, every value is in [0,NN).
// If int32 data is misread as int64, value = lo + hi*2^32 >= 2^32 whenever
// hi != 0; across 64 samples that fires with overwhelming probability.
__global__ void detect_k(const void* ei) {
    if (threadIdx.x == 0 && blockIdx.x == 0) {
        const long long* p = (const long long*)ei;
        int ok = 1;
        for (int i = 0; i < 64; i++) {
            long long v = p[i];
            if (v < 0 || v >= NN) { ok = 0; break; }
        }
        g_is64 = ok;
    }
}

// edge pairs -> int32 with per-graph offset; int degree histogram
__global__ void edges_k(const void* __restrict__ ei) {
    int e = blockIdx.x * blockDim.x + threadIdx.x;
    if (e >= BE) return;
    int r, c;
    if (g_is64) {
        const long long* p = (const long long*)ei;
        r = (int)p[2 * e];
        c = (int)p[2 * e + 1];
    } else {
        const int* p = (const int*)ei;
        r = p[2 * e];
        c = p[2 * e + 1];
    }
    // clamp defensively: wrong answers are diagnosable, crashes are not
    r = min(max(r, 0), NN - 1);
    c = min(max(c, 0), NN - 1);
    int b = e / EE;
    r += b * NN;
    c += b * NN;
    g_row[e] = r;
    g_col[e] = c;
    atomicAdd(&g_degi[r], 1);
}

__global__ void dinv_k() {
    int v = blockIdx.x * blockDim.x + threadIdx.x;
    if (v >= BN) return;
    int d = g_degi[v];
    g_dinv[v] = d > 0 ? rsqrtf((float)d) : 0.f;
}

// single-block exclusive scan of g_degi -> g_rowstart (and g_cursor copy)
__global__ void __launch_bounds__(1024, 1) scan_k() {
    __shared__ int warpsum[32];
    __shared__ int carry_s;
    int tid = threadIdx.x, lane = tid & 31, wid = tid >> 5;
    if (tid == 0) carry_s = 0;
    __syncthreads();
    for (int base = 0; base < BN; base += 1024) {
        int i = base + tid;
        int v = (i < BN) ? g_degi[i] : 0;
        int x = v;
#pragma unroll
        for (int off = 1; off < 32; off <<= 1) {
            int y = __shfl_up_sync(0xffffffffu, x, off);
            if (lane >= off) x += y;
        }
        if (lane == 31) warpsum[wid] = x;
        __syncthreads();
        if (wid == 0) {
            int s = warpsum[lane];
            int xs = s;
#pragma unroll
            for (int off = 1; off < 32; off <<= 1) {
                int y = __shfl_up_sync(0xffffffffu, xs, off);
                if (lane >= off) xs += y;
            }
            warpsum[lane] = xs - s;   // exclusive warp prefix
        }
        __syncthreads();
        int excl = carry_s + warpsum[wid] + (x - v);
        if (i < BN) { g_rowstart[i] = excl; g_cursor[i] = excl; }
        __syncthreads();
        if (tid == 1023) carry_s += warpsum[31] + x;  // chunk total
        __syncthreads();
    }
}

// scatter edges into CSR slots (order within a row is arbitrary)
__global__ void fill_k() {
    int e = blockIdx.x * blockDim.x + threadIdx.x;
    if (e >= BE) return;
    int r = g_row[e], c = g_col[e];
    int pos = atomicAdd(&g_cursor[r], 1);
    float nm = g_dinv[r] * g_dinv[c];
    g_csr[pos] = make_int2(c, __float_as_int(nm));
}

// ---------------------------------------------------------------------------
// t = (relu?)(in) @ W^T + b     [BN,64] x [64,64]; one warp per row
#define LIN_TILES (BN / 8)
template <bool RELU>
__global__ void __launch_bounds__(256, 8)
linear_k(const float* __restrict__ in, const float* __restrict__ W,
         const float* __restrict__ bias, float* __restrict__ out) {
    __shared__ float sW[64 * 65];
    __shared__ float sb[64];
    __shared__ float sx[8][64];
    int tid = threadIdx.x;

    for (int i = tid; i < 64 * 64; i += 256)
        sW[(i >> 6) * 65 + (i & 63)] = W[i];
    if (tid < 64) sb[tid] = bias[tid];

    int w = tid >> 5, l = tid & 31;

    for (int tile = blockIdx.x; tile < LIN_TILES; tile += gridDim.x) {
        int row0 = tile * 8;
        __syncthreads();
        for (int i = tid; i < 8 * 64; i += 256) {
            float v = in[row0 * 64 + i];
            sx[i >> 6][i & 63] = RELU ? fmaxf(v, 0.f) : v;
        }
        __syncthreads();

        float acc0 = sb[l];
        float acc1 = sb[l + 32];
#pragma unroll
        for (int k = 0; k < 64; k++) {
            float xv = sx[w][k];
            acc0 = fmaf(xv, sW[l * 65 + k], acc0);
            acc1 = fmaf(xv, sW[(l + 32) * 65 + k], acc1);
        }
        out[(row0 + w) * 64 + l]      = acc0;
        out[(row0 + w) * 64 + l + 32] = acc1;
    }
}

// ---------------------------------------------------------------------------
// CSR gather SpMM: one warp per node, lanes own features (lane, lane+32)
__global__ void __launch_bounds__(256, 8)
spmm_k(const float* __restrict__ t, float* __restrict__ out) {
    int warp = (blockIdx.x * blockDim.x + threadIdx.x) >> 5;
    if (warp >= BN) return;
    int lane = threadIdx.x & 31;
    int start = g_rowstart[warp];
    int cnt   = g_degi[warp];

    float a0 = 0.f, a1 = 0.f;
    for (int base = 0; base < cnt; base += 32) {
        int m = cnt - base; if (m > 32) m = 32;
        int2 meta = make_int2(0, 0);
        if (lane < m) meta = g_csr[start + base + lane];
#pragma unroll 4
        for (int j = 0; j < m; j++) {
            int   c  = __shfl_sync(0xffffffffu, meta.x, j);
            float nm = __int_as_float(__shfl_sync(0xffffffffu, meta.y, j));
            const float* trow = t + (size_t)c * 64;
            a0 = fmaf(nm, __ldg(trow + lane),      a0);
            a1 = fmaf(nm, __ldg(trow + lane + 32), a1);
        }
    }
    out[(size_t)warp * 64 + lane]      = a0;
    out[(size_t)warp * 64 + lane + 32] = a1;
}

// ---------------------------------------------------------------------------
extern "C" void kernel_launch(void* const* d_in, const int* in_sizes, int n_in,
                              void* d_out, int out_size) {
    // Resolve inputs by element count (robust to metadata ordering):
    //   x          : BN*FF = 5,120,000
    //   edge_index : BE*2  = 2,560,000 (dtype detected on device)
    //   W1,W2,W3   : 4096  (relative order preserved)
    //   b1,b2,b3   : 64    (relative order preserved)
    const float* x = nullptr;
    const void*  ei = nullptr;
    const float* Ws[3] = {nullptr, nullptr, nullptr};
    const float* bs[3] = {nullptr, nullptr, nullptr};
    int nW = 0, nb = 0;
    for (int i = 0; i < n_in; i++) {
        long long sz = in_sizes[i];
        if (sz == (long long)BN * FF)      x  = (const float*)d_in[i];
        else if (sz == (long long)BE * 2)  ei = d_in[i];
        else if (sz == FF * FF) { if (nW < 3) Ws[nW++] = (const float*)d_in[i]; }
        else if (sz == FF)      { if (nb < 3) bs[nb++] = (const float*)d_in[i]; }
    }
    float* out = (float*)d_out;

    int   *degi;
    float *t, *pA, *pB;
    cudaGetSymbolAddress((void**)&degi, g_degi);
    cudaGetSymbolAddress((void**)&t,    g_t);
    cudaGetSymbolAddress((void**)&pA,   g_pA);
    cudaGetSymbolAddress((void**)&pB,   g_pB);

    const int TPB = 256;
    const int edgeBlocks = (BE + TPB - 1) / TPB;            // 5000
    const int nodeBlocks = (BN + TPB - 1) / TPB;            // 313
    const int spmmBlocks = (BN * 32 + TPB - 1) / TPB;       // 10000
    const int linGrid    = 1184;

    // CSR build (once per launch)
    detect_k<<<1, 32>>>(ei);
    zeroi_k<<<nodeBlocks, TPB>>>(degi, BN);
    edges_k<<<edgeBlocks, TPB>>>(ei);
    dinv_k<<<nodeBlocks, TPB>>>();
    scan_k<<<1, 1024>>>();
    fill_k<<<edgeBlocks, TPB>>>();

    // layer 1
    linear_k<false><<<linGrid, TPB>>>(x, Ws[0], bs[0], t);
    spmm_k<<<spmmBlocks, TPB>>>(t, pA);
    // layer 2
    linear_k<true><<<linGrid, TPB>>>(pA, Ws[1], bs[1], t);
    spmm_k<<<spmmBlocks, TPB>>>(t, pB);
    // layer 3
    linear_k<true><<<linGrid, TPB>>>(pB, Ws[2], bs[2], t);
    spmm_k<<<spmmBlocks, TPB>>>(t, out);
}

// round 5
// speedup vs baseline: 1.0452x; 1.0452x over previous
#include <cuda_runtime.h>
#include <cuda_bf16.h>
#include <cstdint>

#define BB 8
#define NN 10000
#define EE 160000
#define FF 64
#define BN (BB * NN)          // 80000 nodes
#define BE (BB * EE)          // 1280000 edges
#define SCAN_BLKS ((BN + 1023) / 1024)   // 79

// ---- scratch (device globals; no allocation allowed) ----
__device__ int   g_is64;
__device__ int   g_degi[BN];
__device__ float g_dinv[BN];
__device__ int   g_rowstart[BN];
__device__ int   g_cursor[BN];
__device__ int   g_scantmp[BN];
__device__ int   g_partial[SCAN_BLKS];
__device__ int2  g_rc[BE];        // packed (row, col)
__device__ int2  g_csr[BE];       // {col, norm-bits} grouped by row
__device__ float g_t[BN * FF];    // post-linear features
__device__ float g_pA[BN * FF];   // ping
__device__ float g_pB[BN * FF];   // pong

// ---------------------------------------------------------------------------
__device__ __forceinline__ void fma2(unsigned long long& acc,
                                     unsigned long long a,
                                     unsigned long long b) {
    asm("fma.rn.f32x2 %0, %1, %2, %0;" : "+l"(acc) : "l"(a), "l"(b));
}
__device__ __forceinline__ unsigned long long pack2(float lo, float hi) {
    unsigned long long r;
    asm("mov.b64 %0, {%1, %2};" : "=l"(r) : "f"(lo), "f"(hi));
    return r;
}
__device__ __forceinline__ void unpack2(unsigned long long v, float& lo, float& hi) {
    asm("mov.b64 {%0, %1}, %2;" : "=f"(lo), "=f"(hi) : "l"(v));
}

// ---------------------------------------------------------------------------
__global__ void zeroi_k(int* __restrict__ p, int n) {
    int i = blockIdx.x * blockDim.x + threadIdx.x;
    for (; i < n; i += gridDim.x * blockDim.x) p[i] = 0;
}

// Detect edge_index width: if int32 data is misread as int64, combined values
// exceed [0,NN) with overwhelming probability across 64 samples.
__global__ void detect_k(const void* ei) {
    if (threadIdx.x == 0 && blockIdx.x == 0) {
        const long long* p = (const long long*)ei;
        int ok = 1;
        for (int i = 0; i < 64; i++) {
            long long v = p[i];
            if (v < 0 || v >= NN) { ok = 0; break; }
        }
        g_is64 = ok;
    }
}

// edge pairs -> int32 with per-graph offset (packed int2); degree histogram
__global__ void edges_k(const void* __restrict__ ei) {
    int e = blockIdx.x * blockDim.x + threadIdx.x;
    if (e >= BE) return;
    int r, c;
    if (g_is64) {
        const long long* p = (const long long*)ei;
        r = (int)p[2 * e];
        c = (int)p[2 * e + 1];
    } else {
        const int* p = (const int*)ei;
        r = p[2 * e];
        c = p[2 * e + 1];
    }
    r = min(max(r, 0), NN - 1);
    c = min(max(c, 0), NN - 1);
    int b = e / EE;
    r += b * NN;
    c += b * NN;
    g_rc[e] = make_int2(r, c);
    atomicAdd(&g_degi[r], 1);
}

// ---- two-level exclusive scan of degrees ----
__global__ void __launch_bounds__(1024, 1) scanA_k() {
    __shared__ int warpsum[32];
    int tid = threadIdx.x, lane = tid & 31, wid = tid >> 5;
    int i = blockIdx.x * 1024 + tid;
    int v = (i < BN) ? g_degi[i] : 0;
    int x = v;
#pragma unroll
    for (int off = 1; off < 32; off <<= 1) {
        int y = __shfl_up_sync(0xffffffffu, x, off);
        if (lane >= off) x += y;
    }
    if (lane == 31) warpsum[wid] = x;
    __syncthreads();
    if (wid == 0) {
        int s = warpsum[lane];
        int xs = s;
#pragma unroll
        for (int off = 1; off < 32; off <<= 1) {
            int y = __shfl_up_sync(0xffffffffu, xs, off);
            if (lane >= off) xs += y;
        }
        warpsum[lane] = xs - s;   // exclusive warp prefix
    }
    __syncthreads();
    int excl = warpsum[wid] + x - v;
    if (i < BN) g_scantmp[i] = excl;
    if (tid == 1023) g_partial[blockIdx.x] = excl + v;  // block total
}

__global__ void scanB_k() {   // 1 warp scans SCAN_BLKS partials
    int lane = threadIdx.x;
    int carry = 0;
    for (int base = 0; base < SCAN_BLKS; base += 32) {
        int idx = base + lane;
        int v = (idx < SCAN_BLKS) ? g_partial[idx] : 0;
        int x = v;
#pragma unroll
        for (int off = 1; off < 32; off <<= 1) {
            int y = __shfl_up_sync(0xffffffffu, x, off);
            if (lane >= off) x += y;
        }
        if (idx < SCAN_BLKS) g_partial[idx] = carry + x - v;
        carry += __shfl_sync(0xffffffffu, x, 31);
    }
}

__global__ void scanC_k() {   // add offsets; also compute dinv (fused)
    int i = blockIdx.x * blockDim.x + threadIdx.x;
    if (i >= BN) return;
    int start = g_scantmp[i] + g_partial[i >> 10];
    g_rowstart[i] = start;
    g_cursor[i]   = start;
    int d = g_degi[i];
    g_dinv[i] = d > 0 ? rsqrtf((float)d) : 0.f;
}

// scatter edges into CSR slots
__global__ void fill_k() {
    int e = blockIdx.x * blockDim.x + threadIdx.x;
    if (e >= BE) return;
    int2 rc = g_rc[e];
    int pos = atomicAdd(&g_cursor[rc.x], 1);
    float nm = g_dinv[rc.x] * g_dinv[rc.y];
    g_csr[pos] = make_int2(rc.y, __float_as_int(nm));
}

// ---------------------------------------------------------------------------
// t = (relu?)(in) @ W^T + b  — packed f32x2, 4 rows per warp, 32 rows per block
template <bool RELU>
__global__ void __launch_bounds__(256)
linear_k(const float* __restrict__ in, const float* __restrict__ W,
         const float* __restrict__ bias, float* __restrict__ out) {
    __shared__ float2 sWp[64 * 32];   // [k][l] = (W[l][k], W[l+32][k])  16KB
    __shared__ float2 sx2[32 * 64];   // [r][k] = (v,v) replicated       16KB
    __shared__ float  sb[64];
    int tid = threadIdx.x;
    int row0 = blockIdx.x * 32;

    for (int idx = tid; idx < 2048; idx += 256) {
        int k = idx >> 5, l = idx & 31;
        sWp[idx] = make_float2(W[l * 64 + k], W[(l + 32) * 64 + k]);
    }
    if (tid < 64) sb[tid] = bias[tid];
    for (int idx = tid; idx < 2048; idx += 256) {
        int r = idx >> 6, k = idx & 63;
        float v = in[(size_t)(row0 + r) * 64 + k];
        if (RELU) v = fmaxf(v, 0.f);
        sx2[idx] = make_float2(v, v);
    }
    __syncthreads();

    int w = tid >> 5, l = tid & 31;
    int r0 = w * 4;
    unsigned long long bias2 = pack2(sb[l], sb[l + 32]);
    unsigned long long a0 = bias2, a1 = bias2, a2 = bias2, a3 = bias2;

    const unsigned long long* wp  = (const unsigned long long*)sWp;
    const unsigned long long* xp  = (const unsigned long long*)sx2;
#pragma unroll
    for (int k = 0; k < 64; k++) {
        unsigned long long wk = wp[k * 32 + l];
        fma2(a0, wk, xp[(r0 + 0) * 64 + k]);
        fma2(a1, wk, xp[(r0 + 1) * 64 + k]);
        fma2(a2, wk, xp[(r0 + 2) * 64 + k]);
        fma2(a3, wk, xp[(r0 + 3) * 64 + k]);
    }
    float lo, hi;
    unpack2(a0, lo, hi); out[(size_t)(row0+r0+0)*64 + l] = lo; out[(size_t)(row0+r0+0)*64 + l + 32] = hi;
    unpack2(a1, lo, hi); out[(size_t)(row0+r0+1)*64 + l] = lo; out[(size_t)(row0+r0+1)*64 + l + 32] = hi;
    unpack2(a2, lo, hi); out[(size_t)(row0+r0+2)*64 + l] = lo; out[(size_t)(row0+r0+2)*64 + l + 32] = hi;
    unpack2(a3, lo, hi); out[(size_t)(row0+r0+3)*64 + l] = lo; out[(size_t)(row0+r0+3)*64 + l + 32] = hi;
}

// ---------------------------------------------------------------------------
// CSR gather SpMM: one warp per node; lane owns features (2l, 2l+1); LDG.64 + FFMA2
__global__ void __launch_bounds__(256, 8)
spmm_k(const float* __restrict__ t, float* __restrict__ out) {
    int warp = (blockIdx.x * blockDim.x + threadIdx.x) >> 5;
    if (warp >= BN) return;
    int lane = threadIdx.x & 31;
    int start = g_rowstart[warp];
    int cnt   = g_degi[warp];

    unsigned long long acc = 0;
    const char* tbase = (const char*)t + (lane << 3);
    for (int base = 0; base < cnt; base += 32) {
        int m = cnt - base; if (m > 32) m = 32;
        int2 meta = make_int2(0, 0);
        if (lane < m) meta = g_csr[start + base + lane];
#pragma unroll 4
        for (int j = 0; j < m; j++) {
            int c   = __shfl_sync(0xffffffffu, meta.x, j);
            int nmb = __shfl_sync(0xffffffffu, meta.y, j);
            unsigned long long nm2;
            asm("mov.b64 %0, {%1, %1};" : "=l"(nm2) : "r"(nmb));
            unsigned long long v;
            asm("ld.global.nc.b64 %0, [%1];" : "=l"(v)
                : "l"(tbase + ((size_t)c << 8)));
            fma2(acc, nm2, v);
        }
    }
    float lo, hi;
    unpack2(acc, lo, hi);
    reinterpret_cast<float2*>(out + (size_t)warp * 64)[lane] = make_float2(lo, hi);
}

// ---------------------------------------------------------------------------
extern "C" void kernel_launch(void* const* d_in, const int* in_sizes, int n_in,
                              void* d_out, int out_size) {
    const float* x = nullptr;
    const void*  ei = nullptr;
    const float* Ws[3] = {nullptr, nullptr, nullptr};
    const float* bs[3] = {nullptr, nullptr, nullptr};
    int nW = 0, nb = 0;
    for (int i = 0; i < n_in; i++) {
        long long sz = in_sizes[i];
        if (sz == (long long)BN * FF)      x  = (const float*)d_in[i];
        else if (sz == (long long)BE * 2)  ei = d_in[i];
        else if (sz == FF * FF) { if (nW < 3) Ws[nW++] = (const float*)d_in[i]; }
        else if (sz == FF)      { if (nb < 3) bs[nb++] = (const float*)d_in[i]; }
    }
    float* out = (float*)d_out;

    int   *degi;
    float *t, *pA, *pB;
    cudaGetSymbolAddress((void**)&degi, g_degi);
    cudaGetSymbolAddress((void**)&t,    g_t);
    cudaGetSymbolAddress((void**)&pA,   g_pA);
    cudaGetSymbolAddress((void**)&pB,   g_pB);

    const int TPB = 256;
    const int edgeBlocks = (BE + TPB - 1) / TPB;            // 5000
    const int nodeBlocks = (BN + TPB - 1) / TPB;            // 313
    const int spmmBlocks = (BN * 32 + TPB - 1) / TPB;       // 10000
    const int linBlocks  = BN / 32;                         // 2500

    // CSR build
    detect_k<<<1, 32>>>(ei);
    zeroi_k<<<nodeBlocks, TPB>>>(degi, BN);
    edges_k<<<edgeBlocks, TPB>>>(ei);
    scanA_k<<<SCAN_BLKS, 1024>>>();
    scanB_k<<<1, 32>>>();
    scanC_k<<<nodeBlocks, TPB>>>();
    fill_k<<<edgeBlocks, TPB>>>();

    // layer 1
    linear_k<false><<<linBlocks, TPB>>>(x, Ws[0], bs[0], t);
    spmm_k<<<spmmBlocks, TPB>>>(t, pA);
    // layer 2
    linear_k<true><<<linBlocks, TPB>>>(pA, Ws[1], bs[1], t);
    spmm_k<<<spmmBlocks, TPB>>>(t, pB);
    // layer 3
    linear_k<true><<<linBlocks, TPB>>>(pB, Ws[2], bs[2], t);
    spmm_k<<<spmmBlocks, TPB>>>(t, out);
}